// round 4
// baseline (speedup 1.0000x reference)
#include <cuda_runtime.h>

// CRPS over a 16-member ensemble:
//   out = mean_p( (1/N) sum_i |s_i - y|  -  (1/N^2) sum_{i<j} |s_i - s_j| )
// Identity: with v sorted ascending, sum_{i<j}|v_i - v_j| = sum_i (2i-15) v_i.
//
// R4: force per-warp MLP=16 — all member loads issued via asm volatile so
// ptxas cannot sink them into the consumer chain (R3 SASS had regs=32 =>
// loads were serialized against math; kernel was DRAM-latency-bound at
// 2.15 TB/s). Single launch, last-block-finishes deterministic reduction.

#define NS 16
#define PIXELS (4 * 1 * 256 * 256)      // 262144
#define TPB 512
#define NBLOCKS (PIXELS / TPB)          // 512

__device__ float g_partials[NBLOCKS];
__device__ unsigned int g_count = 0;

__device__ __forceinline__ float ldg_nc(const float* p) {
    float r;
    asm volatile("ld.global.nc.b32 %0, [%1];" : "=f"(r) : "l"(p));
    return r;
}

__device__ __forceinline__ void cmpswap(float& a, float& b) {
    float lo = fminf(a, b);
    float hi = fmaxf(a, b);
    a = lo; b = hi;
}

__global__ __launch_bounds__(TPB) void crps_fused_kernel(
    const float* __restrict__ samples,   // [NS, PIXELS]
    const float* __restrict__ target,    // [PIXELS]
    float* __restrict__ out)
{
    const int p = blockIdx.x * TPB + threadIdx.x;

    // 17 back-to-back LDGs (asm volatile => cannot be sunk/interleaved).
    float v[NS];
#pragma unroll
    for (int i = 0; i < NS; i++)
        v[i] = ldg_nc(samples + i * PIXELS + p);
    const float y = ldg_nc(target + p);

    // term1: sum_i |v_i - y|  (fma pipe)
    float t1 = 0.f;
#pragma unroll
    for (int i = 0; i < NS; i++)
        t1 += fabsf(v[i] - y);

    // Sort v ascending: Batcher odd-even mergesort, 16 inputs, 63 comparators
    // (126 FMNMX on the alu pipe, overlaps term1's fma-pipe work).
#define CS(a, b) cmpswap(v[a], v[b])
    CS(0,1);  CS(2,3);  CS(4,5);  CS(6,7);  CS(8,9);  CS(10,11); CS(12,13); CS(14,15);
    CS(0,2);  CS(1,3);  CS(4,6);  CS(5,7);  CS(8,10); CS(9,11);  CS(12,14); CS(13,15);
    CS(1,2);  CS(5,6);  CS(9,10); CS(13,14);
    CS(0,4);  CS(1,5);  CS(2,6);  CS(3,7);  CS(8,12); CS(9,13);  CS(10,14); CS(11,15);
    CS(2,4);  CS(3,5);  CS(10,12); CS(11,13);
    CS(1,2);  CS(3,4);  CS(5,6);  CS(9,10); CS(11,12); CS(13,14);
    CS(0,8);  CS(1,9);  CS(2,10); CS(3,11); CS(4,12); CS(5,13);  CS(6,14);  CS(7,15);
    CS(4,8);  CS(5,9);  CS(6,10); CS(7,11);
    CS(2,4);  CS(3,5);  CS(6,8);  CS(7,9);  CS(10,12); CS(11,13);
    CS(1,2);  CS(3,4);  CS(5,6);  CS(7,8);  CS(9,10);  CS(11,12); CS(13,14);
#undef CS

    // term2: sum_{i<j}(v_j - v_i) = sum_i (2i-15) v_i   (16 FFMA)
    float t2 = 0.f;
#pragma unroll
    for (int i = 0; i < NS; i++)
        t2 = fmaf((float)(2 * i - 15), v[i], t2);

    float acc = t1 * (1.f / NS) - t2 * (1.f / (NS * NS));

    // ---- block reduction ----
#pragma unroll
    for (int off = 16; off > 0; off >>= 1)
        acc += __shfl_down_sync(0xFFFFFFFFu, acc, off);

    __shared__ float warp_sums[TPB / 32];
    const int lane = threadIdx.x & 31;
    const int wid  = threadIdx.x >> 5;
    if (lane == 0) warp_sums[wid] = acc;
    __syncthreads();

    __shared__ bool is_last;
    if (threadIdx.x == 0) {
        float bsum = 0.f;
#pragma unroll
        for (int w = 0; w < TPB / 32; w++)
            bsum += warp_sums[w];
        g_partials[blockIdx.x] = bsum;
        __threadfence();
        unsigned int done = atomicAdd(&g_count, 1u);
        is_last = (done == NBLOCKS - 1);
    }
    __syncthreads();

    // ---- last block folds all 512 partials in a fixed order ----
    if (is_last) {
        float s = (threadIdx.x < NBLOCKS) ? g_partials[threadIdx.x] : 0.f;
#pragma unroll
        for (int off = 16; off > 0; off >>= 1)
            s += __shfl_down_sync(0xFFFFFFFFu, s, off);
        if (lane == 0) warp_sums[wid] = s;
        __syncthreads();
        if (wid == 0) {
            float tot = (lane < TPB / 32) ? warp_sums[lane] : 0.f;
#pragma unroll
            for (int off = 8; off > 0; off >>= 1)
                tot += __shfl_down_sync(0xFFFFFFFFu, tot, off);
            if (lane == 0) {
                out[0] = tot * (1.f / PIXELS);
                g_count = 0;   // reset for next graph replay
            }
        }
    }
}

extern "C" void kernel_launch(void* const* d_in, const int* in_sizes, int n_in,
                              void* d_out, int out_size)
{
    const float* samples = (const float*)d_in[0];
    const float* target  = (const float*)d_in[1];
    float* out = (float*)d_out;

    crps_fused_kernel<<<NBLOCKS, TPB>>>(samples, target, out);
}